// round 1
// baseline (speedup 1.0000x reference)
#include <cuda_runtime.h>
#include <cuda_bf16.h>

// DWT_1D: lo/hi[n,c,k] = sum_{j=0..7} tap[j] * x[n,c, 2k+j-3], zero outside [0,SEQ)
// x: (16,64,8192) f32; out: lo (16,64,4096) then hi (16,64,4096), f32.
// Taps are read from the banded matrices: matrix_low[2, 1+j] == REC_LO[j]
// (row k=2 of the band covers columns 1..8 with no boundary clipping).

namespace {
constexpr int SEQ  = 8192;
constexpr int KOUT = 4096;
constexpr int NC   = 16 * 64;   // 1024 rows
constexpr int TPB  = 256;
constexpr int PAD  = 4;         // s[PAD + i] = x[i]; window x[2k-3..2k+4] -> s[2k+1 .. 2k+8]
}

__global__ __launch_bounds__(TPB, 1)
void dwt1d_kernel(const float* __restrict__ x,
                  const float* __restrict__ mlo,
                  const float* __restrict__ mhi,
                  float* __restrict__ out)
{
    __shared__ float s[SEQ + 16];   // [0..3] zero pad, [4..8195] data, [8196..8207] zero pad

    const int row = blockIdx.x;            // 0..1023
    const int t   = threadIdx.x;

    // Zero the pads (front 4 + back 12)
    if (t < 4)            s[t] = 0.0f;
    else if (t < 16)      s[SEQ + t] = 0.0f;   // covers s[8196..8207]

    // Stage the row into smem via float4 (coalesced, 8 per thread)
    {
        const float4* x4 = reinterpret_cast<const float4*>(x + (size_t)row * SEQ);
        #pragma unroll
        for (int i = 0; i < SEQ / 4 / TPB; ++i) {
            int idx = t + i * TPB;
            float4 v = x4[idx];
            int b = PAD + 4 * idx;
            s[b + 0] = v.x; s[b + 1] = v.y; s[b + 2] = v.z; s[b + 3] = v.w;
        }
    }

    // Filter taps straight out of the banded matrices (row 2, cols 1..8).
    float h[8], g[8];
    #pragma unroll
    for (int j = 0; j < 8; ++j) {
        h[j] = __ldg(&mlo[2 * SEQ + 1 + j]);
        g[j] = __ldg(&mhi[2 * SEQ + 1 + j]);
    }

    __syncthreads();

    float4* lo4 = reinterpret_cast<float4*>(out + (size_t)row * KOUT);
    float4* hi4 = reinterpret_cast<float4*>(out + (size_t)NC * KOUT + (size_t)row * KOUT);
    const float4* s4 = reinterpret_cast<const float4*>(s);

    // Each thread computes 4 consecutive outputs (k = 4m .. 4m+3), 4 iterations.
    #pragma unroll
    for (int it = 0; it < KOUT / 4 / TPB; ++it) {
        int m = t + it * TPB;                 // 0..1023
        // Window for k=4m..4m+3 is s[8m+1 .. 8m+14]; load s[8m .. 8m+15] as 4x float4.
        float4 v0 = s4[2 * m + 0];
        float4 v1 = s4[2 * m + 1];
        float4 v2 = s4[2 * m + 2];
        float4 v3 = s4[2 * m + 3];
        float w[16] = { v0.x, v0.y, v0.z, v0.w,
                        v1.x, v1.y, v1.z, v1.w,
                        v2.x, v2.y, v2.z, v2.w,
                        v3.x, v3.y, v3.z, v3.w };

        float lo[4], hi[4];
        #pragma unroll
        for (int p = 0; p < 4; ++p) {
            float a = 0.0f, b = 0.0f;
            #pragma unroll
            for (int j = 0; j < 8; ++j) {
                float xv = w[2 * p + 1 + j];
                a = fmaf(h[j], xv, a);
                b = fmaf(g[j], xv, b);
            }
            lo[p] = a; hi[p] = b;
        }
        lo4[m] = make_float4(lo[0], lo[1], lo[2], lo[3]);
        hi4[m] = make_float4(hi[0], hi[1], hi[2], hi[3]);
    }
}

extern "C" void kernel_launch(void* const* d_in, const int* in_sizes, int n_in,
                              void* d_out, int out_size)
{
    const float* x   = (const float*)d_in[0];
    const float* mlo = (const float*)d_in[1];
    const float* mhi = (const float*)d_in[2];
    float* out = (float*)d_out;

    dwt1d_kernel<<<NC, TPB>>>(x, mlo, mhi, out);
}